// round 5
// baseline (speedup 1.0000x reference)
#include <cuda_runtime.h>

#define USER_NUM 100000
#define ITEM_NUM 50000
#define N_NODES (USER_NUM + ITEM_NUM)
#define D 64
#define D4 (D / 4)
#define NE 4000000
#define NV4 (N_NODES * D4) /* 2,400,000 float4 */

// Scratch (device globals — no runtime allocation allowed)
__device__ float  g_deg_out[N_NODES];
__device__ float  g_deg_in[N_NODES];
__device__ float  g_out_norm[N_NODES];
__device__ float  g_in_norm[N_NODES];
__device__ float4 g_cur[NV4];   // current layer node features
__device__ float4 g_h[NV4];     // pre-scaled features (out_norm applied)
__device__ float4 g_agg[NV4];   // scatter accumulator

// ---------------------------------------------------------------------------
// init: res (d_out) = cur = concat(user_emb, item_emb); zero degree counters
// ---------------------------------------------------------------------------
__global__ void init_kernel(const float4* __restrict__ ue,
                            const float4* __restrict__ ie,
                            float4* __restrict__ out) {
    int i = blockIdx.x * blockDim.x + threadIdx.x;
    if (i < NV4) {
        float4 v = (i < USER_NUM * D4) ? __ldg(&ue[i])
                                       : __ldg(&ie[i - USER_NUM * D4]);
        g_cur[i] = v;
        out[i]   = v;
    }
    if (i < N_NODES) {
        g_deg_out[i] = 0.f;
        g_deg_in[i]  = 0.f;
    }
}

// ---------------------------------------------------------------------------
// degree histogram over edges
// ---------------------------------------------------------------------------
__global__ void deg_kernel(const int* __restrict__ src,
                           const int* __restrict__ dst) {
    int e = blockIdx.x * blockDim.x + threadIdx.x;
    if (e < NE) {
        atomicAdd(&g_deg_out[__ldg(&src[e])], 1.f);
        atomicAdd(&g_deg_in[__ldg(&dst[e])], 1.f);
    }
}

// ---------------------------------------------------------------------------
// norms: deg^-0.5 with clip(deg, 1)
// ---------------------------------------------------------------------------
__global__ void norm_kernel() {
    int v = blockIdx.x * blockDim.x + threadIdx.x;
    if (v < N_NODES) {
        g_out_norm[v] = rsqrtf(fmaxf(g_deg_out[v], 1.f));
        g_in_norm[v]  = rsqrtf(fmaxf(g_deg_in[v], 1.f));
    }
}

// ---------------------------------------------------------------------------
// per-layer prologue: h = cur * out_norm ; agg = 0
// ---------------------------------------------------------------------------
__global__ void prep_kernel() {
    int i = blockIdx.x * blockDim.x + threadIdx.x;
    if (i >= NV4) return;
    float s  = g_out_norm[i >> 4];  // 16 float4 per node row
    float4 v = g_cur[i];
    v.x *= s; v.y *= s; v.z *= s; v.w *= s;
    g_h[i]   = v;
    g_agg[i] = make_float4(0.f, 0.f, 0.f, 0.f);
}

// ---------------------------------------------------------------------------
// edge scatter: agg[dst] += h[src]; 16 threads per edge, float4 atomics
// ---------------------------------------------------------------------------
__global__ void scatter_kernel(const int* __restrict__ src,
                               const int* __restrict__ dst) {
    long long t = (long long)blockIdx.x * blockDim.x + threadIdx.x;
    int lane    = (int)(t & 15);
    long long e = t >> 4;
    if (e >= NE) return;
    int s = __ldg(&src[e]);
    int d = __ldg(&dst[e]);
    float4 v = g_h[s * D4 + lane];
    atomicAdd(&g_agg[d * D4 + lane], v);  // sm_90+ vector RED at L2
}

// ---------------------------------------------------------------------------
// per-layer epilogue: emb = agg * in_norm ; cur = emb ; res += emb * scale
// ---------------------------------------------------------------------------
__global__ void post_kernel(float4* __restrict__ out, float scale) {
    int i = blockIdx.x * blockDim.x + threadIdx.x;
    if (i >= NV4) return;
    float s  = g_in_norm[i >> 4];
    float4 a = g_agg[i];
    a.x *= s; a.y *= s; a.z *= s; a.w *= s;
    g_cur[i] = a;
    float4 o = out[i];
    o.x += a.x * scale; o.y += a.y * scale;
    o.z += a.z * scale; o.w += a.w * scale;
    out[i] = o;
}

// ---------------------------------------------------------------------------
// launch
// ---------------------------------------------------------------------------
extern "C" void kernel_launch(void* const* d_in, const int* in_sizes, int n_in,
                              void* d_out, int out_size) {
    const float4* ue  = (const float4*)d_in[0];
    const float4* ie  = (const float4*)d_in[1];
    const int*    src = (const int*)d_in[2];
    const int*    dst = (const int*)d_in[3];
    float4*       out = (float4*)d_out;

    const int T = 256;
    const int gElem = (NV4 + T - 1) / T;

    init_kernel<<<gElem, T>>>(ue, ie, out);
    deg_kernel<<<(NE + T - 1) / T, T>>>(src, dst);
    norm_kernel<<<(N_NODES + T - 1) / T, T>>>();

    const long long scatterThreads = (long long)NE * 16;
    const int gScatter = (int)((scatterThreads + T - 1) / T);

    for (int l = 0; l < 3; l++) {
        prep_kernel<<<gElem, T>>>();
        scatter_kernel<<<gScatter, T>>>(src, dst);
        post_kernel<<<gElem, T>>>(out, 1.0f / (float)(l + 2));
    }
}

// round 10
// speedup vs baseline: 1.5246x; 1.5246x over previous
#include <cuda_runtime.h>

#define USER_NUM 100000
#define ITEM_NUM 50000
#define N_NODES (USER_NUM + ITEM_NUM)
#define D 64
#define D4 (D / 4)
#define NE 4000000
#define NV4 (N_NODES * D4) /* 2,400,000 float4 */

// ---- device scratch (no runtime allocation allowed) ----
__device__ int    g_ideg_out[N_NODES];
__device__ int    g_ideg_in[N_NODES];
__device__ float  g_out_norm[N_NODES];
__device__ float  g_in_norm[N_NODES];
__device__ int    g_off[N_NODES + 1];   // CSR row offsets (by dst)
__device__ int    g_cursor[N_NODES];    // fill cursors
__device__ int    g_csr[NE];            // src indices grouped by dst
__device__ float4 g_hA[NV4];            // ping-pong pre-scaled features
__device__ float4 g_hB[NV4];

// ---------------------------------------------------------------------------
// init: out = concat(user_emb, item_emb); zero degree counters
// ---------------------------------------------------------------------------
__global__ void init_kernel(const float4* __restrict__ ue,
                            const float4* __restrict__ ie,
                            float4* __restrict__ out) {
    int i = blockIdx.x * blockDim.x + threadIdx.x;
    if (i < NV4) {
        float4 v = (i < USER_NUM * D4) ? __ldg(&ue[i])
                                       : __ldg(&ie[i - USER_NUM * D4]);
        out[i] = v;
    }
    if (i < N_NODES) {
        g_ideg_out[i] = 0;
        g_ideg_in[i]  = 0;
    }
}

// ---------------------------------------------------------------------------
// integer degree histogram
// ---------------------------------------------------------------------------
__global__ void deg_kernel(const int* __restrict__ src,
                           const int* __restrict__ dst) {
    int e = blockIdx.x * blockDim.x + threadIdx.x;
    if (e < NE) {
        atomicAdd(&g_ideg_out[__ldg(&src[e])], 1);
        atomicAdd(&g_ideg_in[__ldg(&dst[e])], 1);
    }
}

// ---------------------------------------------------------------------------
// norms (deg^-0.5, clipped at 1) + zero cursors
// ---------------------------------------------------------------------------
__global__ void norm_kernel() {
    int v = blockIdx.x * blockDim.x + threadIdx.x;
    if (v < N_NODES) {
        g_out_norm[v] = rsqrtf(fmaxf((float)g_ideg_out[v], 1.f));
        g_in_norm[v]  = rsqrtf(fmaxf((float)g_ideg_in[v], 1.f));
        g_cursor[v]   = 0;
    }
}

// ---------------------------------------------------------------------------
// single-block exclusive scan of in-degrees -> CSR offsets
// ---------------------------------------------------------------------------
__global__ void scan_kernel() {
    __shared__ int buf[1024];
    __shared__ int carry;
    if (threadIdx.x == 0) carry = 0;
    __syncthreads();
    for (int base = 0; base < N_NODES; base += 1024) {
        int i = base + (int)threadIdx.x;
        int v = (i < N_NODES) ? g_ideg_in[i] : 0;
        buf[threadIdx.x] = v;
        __syncthreads();
        #pragma unroll
        for (int o = 1; o < 1024; o <<= 1) {
            int t = (threadIdx.x >= o) ? buf[threadIdx.x - o] : 0;
            __syncthreads();
            buf[threadIdx.x] += t;
            __syncthreads();
        }
        int incl = buf[threadIdx.x];
        if (i < N_NODES) g_off[i] = carry + incl - v;   // exclusive
        __syncthreads();
        if (threadIdx.x == 0) carry += buf[1023];
        __syncthreads();
    }
    if (threadIdx.x == 0) g_off[N_NODES] = carry;       // == NE
}

// ---------------------------------------------------------------------------
// CSR fill: bucket src indices by dst
// ---------------------------------------------------------------------------
__global__ void fill_kernel(const int* __restrict__ src,
                            const int* __restrict__ dst) {
    int e = blockIdx.x * blockDim.x + threadIdx.x;
    if (e < NE) {
        int d = __ldg(&dst[e]);
        int pos = atomicAdd(&g_cursor[d], 1);
        g_csr[g_off[d] + pos] = __ldg(&src[e]);
    }
}

// ---------------------------------------------------------------------------
// layer-0 prologue: hA = out * out_norm  (out holds the initial embeddings)
// ---------------------------------------------------------------------------
__global__ void prep_kernel(const float4* __restrict__ out) {
    int i = blockIdx.x * blockDim.x + threadIdx.x;
    if (i >= NV4) return;
    float s  = g_out_norm[i >> 4];
    float4 v = out[i];
    v.x *= s; v.y *= s; v.z *= s; v.w *= s;
    g_hA[i] = v;
}

// ---------------------------------------------------------------------------
// fused layer: register-accumulated pull gather + in_norm + residual +
// pre-scaled h for the next layer. 16 threads per dst node (one float4 each).
// ping=0: read hA write hB; ping=1: read hB write hA.
// ---------------------------------------------------------------------------
__global__ void __launch_bounds__(256)
layer_kernel(float4* __restrict__ out, float scale, int ping, int write_h) {
    int t    = blockIdx.x * blockDim.x + threadIdx.x;
    int lane = t & 15;
    int v    = t >> 4;
    if (v >= N_NODES) return;

    const float4* __restrict__ hin  = ping ? g_hB : g_hA;
    float4* __restrict__       hout = ping ? g_hA : g_hB;

    int beg = __ldg(&g_off[v]);
    int end = __ldg(&g_off[v + 1]);

    float4 a0 = make_float4(0.f, 0.f, 0.f, 0.f);
    float4 a1 = make_float4(0.f, 0.f, 0.f, 0.f);

    int j = beg;
    for (; j + 3 < end; j += 4) {
        int s0 = __ldg(&g_csr[j]);
        int s1 = __ldg(&g_csr[j + 1]);
        int s2 = __ldg(&g_csr[j + 2]);
        int s3 = __ldg(&g_csr[j + 3]);
        float4 x0 = __ldg(&hin[s0 * D4 + lane]);
        float4 x1 = __ldg(&hin[s1 * D4 + lane]);
        float4 x2 = __ldg(&hin[s2 * D4 + lane]);
        float4 x3 = __ldg(&hin[s3 * D4 + lane]);
        a0.x += x0.x; a0.y += x0.y; a0.z += x0.z; a0.w += x0.w;
        a1.x += x1.x; a1.y += x1.y; a1.z += x1.z; a1.w += x1.w;
        a0.x += x2.x; a0.y += x2.y; a0.z += x2.z; a0.w += x2.w;
        a1.x += x3.x; a1.y += x3.y; a1.z += x3.z; a1.w += x3.w;
    }
    for (; j < end; j++) {
        int s = __ldg(&g_csr[j]);
        float4 x = __ldg(&hin[s * D4 + lane]);
        a0.x += x.x; a0.y += x.y; a0.z += x.z; a0.w += x.w;
    }

    float inn = __ldg(&g_in_norm[v]);
    float4 emb;
    emb.x = (a0.x + a1.x) * inn;
    emb.y = (a0.y + a1.y) * inn;
    emb.z = (a0.z + a1.z) * inn;
    emb.w = (a0.w + a1.w) * inn;

    int idx = v * D4 + lane;

    if (write_h) {
        float onn = __ldg(&g_out_norm[v]);
        float4 h;
        h.x = emb.x * onn; h.y = emb.y * onn;
        h.z = emb.z * onn; h.w = emb.w * onn;
        hout[idx] = h;
    }

    float4 o = out[idx];
    o.x += emb.x * scale; o.y += emb.y * scale;
    o.z += emb.z * scale; o.w += emb.w * scale;
    out[idx] = o;
}

// ---------------------------------------------------------------------------
// launch
// ---------------------------------------------------------------------------
extern "C" void kernel_launch(void* const* d_in, const int* in_sizes, int n_in,
                              void* d_out, int out_size) {
    const float4* ue  = (const float4*)d_in[0];
    const float4* ie  = (const float4*)d_in[1];
    const int*    src = (const int*)d_in[2];
    const int*    dst = (const int*)d_in[3];
    float4*       out = (float4*)d_out;

    const int T = 256;
    const int gElem = (NV4 + T - 1) / T;
    const int gEdge = (NE + T - 1) / T;

    init_kernel<<<gElem, T>>>(ue, ie, out);
    deg_kernel<<<gEdge, T>>>(src, dst);
    norm_kernel<<<(N_NODES + T - 1) / T, T>>>();
    scan_kernel<<<1, 1024>>>();
    fill_kernel<<<gEdge, T>>>(src, dst);
    prep_kernel<<<gElem, T>>>(out);

    const int gLayer = (N_NODES * 16 + T - 1) / T;
    for (int l = 0; l < 3; l++) {
        layer_kernel<<<gLayer, T>>>(out, 1.0f / (float)(l + 2), l & 1, l < 2);
    }
}

// round 15
// speedup vs baseline: 2.3273x; 1.5265x over previous
#include <cuda_runtime.h>

#define USER_NUM 100000
#define ITEM_NUM 50000
#define N_NODES (USER_NUM + ITEM_NUM)
#define D 64
#define D4 (D / 4)
#define NE 4000000
#define NV4 (N_NODES * D4) /* 2,400,000 float4 */

#define SCAN_B 1024
#define SCAN_NB ((N_NODES + SCAN_B - 1) / SCAN_B)   /* 147 */

// ---- device scratch (no runtime allocation allowed) ----
__device__ int    g_ideg_out[N_NODES];
__device__ int    g_ideg_in[N_NODES];
__device__ float  g_out_norm[N_NODES];
__device__ float  g_in_norm[N_NODES];
__device__ int    g_off[N_NODES + 1];   // CSR row offsets (by dst)
__device__ int    g_cursor[N_NODES];    // absolute fill cursors
__device__ int    g_bsum[SCAN_NB];      // per-block scan sums
__device__ int    g_csr[NE];            // src indices grouped by dst
__device__ float4 g_hA[NV4];            // ping-pong pre-scaled features
__device__ float4 g_hB[NV4];

// ---------------------------------------------------------------------------
// init: out = concat(user_emb, item_emb); zero degree counters
// ---------------------------------------------------------------------------
__global__ void init_kernel(const float4* __restrict__ ue,
                            const float4* __restrict__ ie,
                            float4* __restrict__ out) {
    int i = blockIdx.x * blockDim.x + threadIdx.x;
    if (i < NV4) {
        float4 v = (i < USER_NUM * D4) ? __ldg(&ue[i])
                                       : __ldg(&ie[i - USER_NUM * D4]);
        out[i] = v;
    }
    if (i < N_NODES) {
        g_ideg_out[i] = 0;
        g_ideg_in[i]  = 0;
    }
}

// ---------------------------------------------------------------------------
// integer degree histogram
// ---------------------------------------------------------------------------
__global__ void deg_kernel(const int* __restrict__ src,
                           const int* __restrict__ dst) {
    int e = blockIdx.x * blockDim.x + threadIdx.x;
    if (e < NE) {
        atomicAdd(&g_ideg_out[__ldg(&src[e])], 1);
        atomicAdd(&g_ideg_in[__ldg(&dst[e])], 1);
    }
}

// ---------------------------------------------------------------------------
// norms (deg^-0.5, clipped at 1)
// ---------------------------------------------------------------------------
__global__ void norm_kernel() {
    int v = blockIdx.x * blockDim.x + threadIdx.x;
    if (v < N_NODES) {
        g_out_norm[v] = rsqrtf(fmaxf((float)g_ideg_out[v], 1.f));
        g_in_norm[v]  = rsqrtf(fmaxf((float)g_ideg_in[v], 1.f));
    }
}

// ---------------------------------------------------------------------------
// scan pass 1: per-block exclusive scan of in-degrees (warp shuffle),
// writes local exclusive prefixes to g_off and block total to g_bsum.
// ---------------------------------------------------------------------------
__global__ void __launch_bounds__(SCAN_B)
scan1_kernel() {
    __shared__ int wsum[SCAN_B / 32];
    int i    = blockIdx.x * SCAN_B + threadIdx.x;
    int lane = threadIdx.x & 31;
    int warp = threadIdx.x >> 5;

    int v = (i < N_NODES) ? g_ideg_in[i] : 0;

    // warp inclusive scan
    int incl = v;
    #pragma unroll
    for (int o = 1; o < 32; o <<= 1) {
        int t = __shfl_up_sync(0xffffffff, incl, o);
        if (lane >= o) incl += t;
    }
    if (lane == 31) wsum[warp] = incl;
    __syncthreads();

    // scan the 32 warp sums in warp 0
    if (warp == 0) {
        int ws = wsum[lane];
        #pragma unroll
        for (int o = 1; o < 32; o <<= 1) {
            int t = __shfl_up_sync(0xffffffff, ws, o);
            if (lane >= o) ws += t;
        }
        wsum[lane] = ws;   // inclusive over warp sums
    }
    __syncthreads();

    int warp_base = (warp == 0) ? 0 : wsum[warp - 1];
    int excl = warp_base + incl - v;
    if (i < N_NODES) g_off[i] = excl;            // block-local exclusive
    if (threadIdx.x == SCAN_B - 1) g_bsum[blockIdx.x] = wsum[31];
}

// ---------------------------------------------------------------------------
// scan pass 2: one block scans the SCAN_NB block sums (exclusive, in place)
// ---------------------------------------------------------------------------
__global__ void scan2_kernel() {
    __shared__ int buf[256];
    int t = threadIdx.x;
    int v = (t < SCAN_NB) ? g_bsum[t] : 0;
    buf[t] = v;
    __syncthreads();
    #pragma unroll
    for (int o = 1; o < 256; o <<= 1) {
        int x = (t >= o) ? buf[t - o] : 0;
        __syncthreads();
        buf[t] += x;
        __syncthreads();
    }
    if (t < SCAN_NB) g_bsum[t] = buf[t] - v;     // exclusive
}

// ---------------------------------------------------------------------------
// scan pass 3: add block bases; seed cursors with absolute offsets
// ---------------------------------------------------------------------------
__global__ void scan3_kernel() {
    int i = blockIdx.x * blockDim.x + threadIdx.x;
    if (i < N_NODES) {
        int o = g_off[i] + g_bsum[i / SCAN_B];
        g_off[i]    = o;
        g_cursor[i] = o;
    }
    if (i == 0) g_off[N_NODES] = NE;
}

// ---------------------------------------------------------------------------
// CSR fill: cursor already holds the absolute base offset
// ---------------------------------------------------------------------------
__global__ void fill_kernel(const int* __restrict__ src,
                            const int* __restrict__ dst) {
    int e = blockIdx.x * blockDim.x + threadIdx.x;
    if (e < NE) {
        int d   = __ldg(&dst[e]);
        int pos = atomicAdd(&g_cursor[d], 1);
        g_csr[pos] = __ldg(&src[e]);
    }
}

// ---------------------------------------------------------------------------
// layer-0 prologue: hA = out * out_norm  (out holds the initial embeddings)
// ---------------------------------------------------------------------------
__global__ void prep_kernel(const float4* __restrict__ out) {
    int i = blockIdx.x * blockDim.x + threadIdx.x;
    if (i >= NV4) return;
    float s  = g_out_norm[i >> 4];
    float4 v = out[i];
    v.x *= s; v.y *= s; v.z *= s; v.w *= s;
    g_hA[i] = v;
}

// ---------------------------------------------------------------------------
// fused layer: register-accumulated pull gather + in_norm + residual +
// pre-scaled h for the next layer. 16 threads per dst node (one float4 each).
// ---------------------------------------------------------------------------
__global__ void __launch_bounds__(256)
layer_kernel(float4* __restrict__ out, float scale, int ping, int write_h) {
    int t    = blockIdx.x * blockDim.x + threadIdx.x;
    int lane = t & 15;
    int v    = t >> 4;
    if (v >= N_NODES) return;

    const float4* __restrict__ hin  = ping ? g_hB : g_hA;
    float4* __restrict__       hout = ping ? g_hA : g_hB;

    int beg = __ldg(&g_off[v]);
    int end = __ldg(&g_off[v + 1]);

    float4 a0 = make_float4(0.f, 0.f, 0.f, 0.f);
    float4 a1 = make_float4(0.f, 0.f, 0.f, 0.f);

    int j = beg;
    for (; j + 3 < end; j += 4) {
        int s0 = __ldg(&g_csr[j]);
        int s1 = __ldg(&g_csr[j + 1]);
        int s2 = __ldg(&g_csr[j + 2]);
        int s3 = __ldg(&g_csr[j + 3]);
        float4 x0 = __ldg(&hin[s0 * D4 + lane]);
        float4 x1 = __ldg(&hin[s1 * D4 + lane]);
        float4 x2 = __ldg(&hin[s2 * D4 + lane]);
        float4 x3 = __ldg(&hin[s3 * D4 + lane]);
        a0.x += x0.x; a0.y += x0.y; a0.z += x0.z; a0.w += x0.w;
        a1.x += x1.x; a1.y += x1.y; a1.z += x1.z; a1.w += x1.w;
        a0.x += x2.x; a0.y += x2.y; a0.z += x2.z; a0.w += x2.w;
        a1.x += x3.x; a1.y += x3.y; a1.z += x3.z; a1.w += x3.w;
    }
    for (; j < end; j++) {
        int s = __ldg(&g_csr[j]);
        float4 x = __ldg(&hin[s * D4 + lane]);
        a0.x += x.x; a0.y += x.y; a0.z += x.z; a0.w += x.w;
    }

    float inn = __ldg(&g_in_norm[v]);
    float4 emb;
    emb.x = (a0.x + a1.x) * inn;
    emb.y = (a0.y + a1.y) * inn;
    emb.z = (a0.z + a1.z) * inn;
    emb.w = (a0.w + a1.w) * inn;

    int idx = v * D4 + lane;

    if (write_h) {
        float onn = __ldg(&g_out_norm[v]);
        float4 h;
        h.x = emb.x * onn; h.y = emb.y * onn;
        h.z = emb.z * onn; h.w = emb.w * onn;
        hout[idx] = h;
    }

    float4 o = out[idx];
    o.x += emb.x * scale; o.y += emb.y * scale;
    o.z += emb.z * scale; o.w += emb.w * scale;
    out[idx] = o;
}

// ---------------------------------------------------------------------------
// launch
// ---------------------------------------------------------------------------
extern "C" void kernel_launch(void* const* d_in, const int* in_sizes, int n_in,
                              void* d_out, int out_size) {
    const float4* ue  = (const float4*)d_in[0];
    const float4* ie  = (const float4*)d_in[1];
    const int*    src = (const int*)d_in[2];
    const int*    dst = (const int*)d_in[3];
    float4*       out = (float4*)d_out;

    const int T = 256;
    const int gElem = (NV4 + T - 1) / T;
    const int gEdge = (NE + T - 1) / T;
    const int gNode = (N_NODES + T - 1) / T;

    init_kernel<<<gElem, T>>>(ue, ie, out);
    deg_kernel<<<gEdge, T>>>(src, dst);
    norm_kernel<<<gNode, T>>>();
    scan1_kernel<<<SCAN_NB, SCAN_B>>>();
    scan2_kernel<<<1, 256>>>();
    scan3_kernel<<<gNode, T>>>();
    fill_kernel<<<gEdge, T>>>(src, dst);
    prep_kernel<<<gElem, T>>>(out);

    const int gLayer = (N_NODES * 16 + T - 1) / T;
    for (int l = 0; l < 3; l++) {
        layer_kernel<<<gLayer, T>>>(out, 1.0f / (float)(l + 2), l & 1, l < 2);
    }
}

// round 16
// speedup vs baseline: 2.4471x; 1.0515x over previous
#include <cuda_runtime.h>

#define USER_NUM 100000
#define ITEM_NUM 50000
#define N_NODES (USER_NUM + ITEM_NUM)
#define D 64
#define D4 (D / 4)
#define NE 4000000
#define NV4 (N_NODES * D4) /* 2,400,000 float4 */

#define SCAN_B 1024
#define SCAN_NB ((N_NODES + SCAN_B - 1) / SCAN_B)   /* 147 */

// ---- device scratch (no runtime allocation allowed) ----
__device__ int    g_ideg_out[N_NODES];
__device__ int    g_ideg_in[N_NODES];
__device__ float  g_out_norm[N_NODES];
__device__ float  g_in_norm[N_NODES];
__device__ int    g_off[N_NODES + 1];   // CSR row offsets (by dst)
__device__ int    g_cursor[N_NODES];    // absolute fill cursors
__device__ int    g_bsum[SCAN_NB];      // per-block scan sums
__device__ int    g_csr[NE];            // src indices grouped by dst
__device__ float4 g_e1[NV4];            // layer-1 raw embeddings
__device__ float4 g_e2[NV4];            // layer-2 raw embeddings

// ---------------------------------------------------------------------------
// zero degree counters
// ---------------------------------------------------------------------------
__global__ void zero_kernel() {
    int i = blockIdx.x * blockDim.x + threadIdx.x;
    if (i < N_NODES) {
        g_ideg_out[i] = 0;
        g_ideg_in[i]  = 0;
    }
}

// ---------------------------------------------------------------------------
// integer degree histogram, 4 edges per thread (int4 loads)
// ---------------------------------------------------------------------------
__global__ void deg_kernel(const int4* __restrict__ src4,
                           const int4* __restrict__ dst4) {
    int q = blockIdx.x * blockDim.x + threadIdx.x;
    if (q < NE / 4) {
        int4 s = __ldg(&src4[q]);
        int4 d = __ldg(&dst4[q]);
        atomicAdd(&g_ideg_out[s.x], 1);
        atomicAdd(&g_ideg_out[s.y], 1);
        atomicAdd(&g_ideg_out[s.z], 1);
        atomicAdd(&g_ideg_out[s.w], 1);
        atomicAdd(&g_ideg_in[d.x], 1);
        atomicAdd(&g_ideg_in[d.y], 1);
        atomicAdd(&g_ideg_in[d.z], 1);
        atomicAdd(&g_ideg_in[d.w], 1);
    }
}

// ---------------------------------------------------------------------------
// scan pass 1: per-block exclusive scan of in-degrees (warp shuffle)
// ---------------------------------------------------------------------------
__global__ void __launch_bounds__(SCAN_B)
scan1_kernel() {
    __shared__ int wsum[SCAN_B / 32];
    int i    = blockIdx.x * SCAN_B + threadIdx.x;
    int lane = threadIdx.x & 31;
    int warp = threadIdx.x >> 5;

    int v = (i < N_NODES) ? g_ideg_in[i] : 0;

    int incl = v;
    #pragma unroll
    for (int o = 1; o < 32; o <<= 1) {
        int t = __shfl_up_sync(0xffffffff, incl, o);
        if (lane >= o) incl += t;
    }
    if (lane == 31) wsum[warp] = incl;
    __syncthreads();

    if (warp == 0) {
        int ws = wsum[lane];
        #pragma unroll
        for (int o = 1; o < 32; o <<= 1) {
            int t = __shfl_up_sync(0xffffffff, ws, o);
            if (lane >= o) ws += t;
        }
        wsum[lane] = ws;
    }
    __syncthreads();

    int warp_base = (warp == 0) ? 0 : wsum[warp - 1];
    if (i < N_NODES) g_off[i] = warp_base + incl - v;   // block-local exclusive
    if (threadIdx.x == SCAN_B - 1) g_bsum[blockIdx.x] = wsum[31];
}

// ---------------------------------------------------------------------------
// scan pass 2: one block scans the SCAN_NB block sums (exclusive, in place)
// ---------------------------------------------------------------------------
__global__ void scan2_kernel() {
    __shared__ int buf[256];
    int t = threadIdx.x;
    int v = (t < SCAN_NB) ? g_bsum[t] : 0;
    buf[t] = v;
    __syncthreads();
    #pragma unroll
    for (int o = 1; o < 256; o <<= 1) {
        int x = (t >= o) ? buf[t - o] : 0;
        __syncthreads();
        buf[t] += x;
        __syncthreads();
    }
    if (t < SCAN_NB) g_bsum[t] = buf[t] - v;
}

// ---------------------------------------------------------------------------
// scan pass 3: absolute offsets + cursors + fused norm computation
// ---------------------------------------------------------------------------
__global__ void scan3_kernel() {
    int i = blockIdx.x * blockDim.x + threadIdx.x;
    if (i < N_NODES) {
        int o = g_off[i] + g_bsum[i / SCAN_B];
        g_off[i]      = o;
        g_cursor[i]   = o;
        g_out_norm[i] = rsqrtf(fmaxf((float)g_ideg_out[i], 1.f));
        g_in_norm[i]  = rsqrtf(fmaxf((float)g_ideg_in[i], 1.f));
    }
    if (i == 0) g_off[N_NODES] = NE;
}

// ---------------------------------------------------------------------------
// CSR fill: cursor already holds the absolute base offset
// ---------------------------------------------------------------------------
__global__ void fill_kernel(const int* __restrict__ src,
                            const int* __restrict__ dst) {
    int e = blockIdx.x * blockDim.x + threadIdx.x;
    if (e < NE) {
        int d   = __ldg(&dst[e]);
        int pos = atomicAdd(&g_cursor[d], 1);
        g_csr[pos] = __ldg(&src[e]);
    }
}

// ---------------------------------------------------------------------------
// gather body: accumulate sum over neighbors of (row[src] * out_norm[src]).
// 16 threads per node, one float4 lane each. SrcFetch returns the row ptr.
// ---------------------------------------------------------------------------
__device__ __forceinline__ const float4* e0_row(const float4* ue, const float4* ie, int s) {
    return (s < USER_NUM) ? (ue + (size_t)s * D4)
                          : (ie + (size_t)(s - USER_NUM) * D4);
}

#define GATHER_LOOP(ROW_EXPR)                                                  \
    float4 a0 = make_float4(0.f, 0.f, 0.f, 0.f);                               \
    float4 a1 = make_float4(0.f, 0.f, 0.f, 0.f);                               \
    int j = beg;                                                               \
    for (; j + 3 < end; j += 4) {                                              \
        int s0 = __ldg(&g_csr[j]);                                             \
        int s1 = __ldg(&g_csr[j + 1]);                                         \
        int s2 = __ldg(&g_csr[j + 2]);                                         \
        int s3 = __ldg(&g_csr[j + 3]);                                         \
        float n0 = __ldg(&g_out_norm[s0]);                                     \
        float n1 = __ldg(&g_out_norm[s1]);                                     \
        float n2 = __ldg(&g_out_norm[s2]);                                     \
        float n3 = __ldg(&g_out_norm[s3]);                                     \
        float4 x0 = __ldg(ROW_EXPR(s0) + lane);                                \
        float4 x1 = __ldg(ROW_EXPR(s1) + lane);                                \
        float4 x2 = __ldg(ROW_EXPR(s2) + lane);                                \
        float4 x3 = __ldg(ROW_EXPR(s3) + lane);                                \
        a0.x += x0.x * n0; a0.y += x0.y * n0; a0.z += x0.z * n0; a0.w += x0.w * n0; \
        a1.x += x1.x * n1; a1.y += x1.y * n1; a1.z += x1.z * n1; a1.w += x1.w * n1; \
        a0.x += x2.x * n2; a0.y += x2.y * n2; a0.z += x2.z * n2; a0.w += x2.w * n2; \
        a1.x += x3.x * n3; a1.y += x3.y * n3; a1.z += x3.z * n3; a1.w += x3.w * n3; \
    }                                                                          \
    for (; j < end; j++) {                                                     \
        int s = __ldg(&g_csr[j]);                                              \
        float n = __ldg(&g_out_norm[s]);                                       \
        float4 x = __ldg(ROW_EXPR(s) + lane);                                  \
        a0.x += x.x * n; a0.y += x.y * n; a0.z += x.z * n; a0.w += x.w * n;    \
    }

// ---------------------------------------------------------------------------
// layer 1: gather from initial embeddings (ue/ie), write raw e1
// ---------------------------------------------------------------------------
__global__ void __launch_bounds__(256)
layer1_kernel(const float4* __restrict__ ue, const float4* __restrict__ ie) {
    int t    = blockIdx.x * blockDim.x + threadIdx.x;
    int lane = t & 15;
    int v    = t >> 4;
    if (v >= N_NODES) return;
    int beg = __ldg(&g_off[v]);
    int end = __ldg(&g_off[v + 1]);

#define ROW_E0(s) e0_row(ue, ie, s)
    GATHER_LOOP(ROW_E0)
#undef ROW_E0

    float inn = __ldg(&g_in_norm[v]);
    float4 emb;
    emb.x = (a0.x + a1.x) * inn;
    emb.y = (a0.y + a1.y) * inn;
    emb.z = (a0.z + a1.z) * inn;
    emb.w = (a0.w + a1.w) * inn;
    g_e1[v * D4 + lane] = emb;
}

// ---------------------------------------------------------------------------
// layer 2: gather from e1, write raw e2
// ---------------------------------------------------------------------------
__global__ void __launch_bounds__(256)
layer2_kernel() {
    int t    = blockIdx.x * blockDim.x + threadIdx.x;
    int lane = t & 15;
    int v    = t >> 4;
    if (v >= N_NODES) return;
    int beg = __ldg(&g_off[v]);
    int end = __ldg(&g_off[v + 1]);

#define ROW_E1(s) (g_e1 + (size_t)(s) * D4)
    GATHER_LOOP(ROW_E1)
#undef ROW_E1

    float inn = __ldg(&g_in_norm[v]);
    float4 emb;
    emb.x = (a0.x + a1.x) * inn;
    emb.y = (a0.y + a1.y) * inn;
    emb.z = (a0.z + a1.z) * inn;
    emb.w = (a0.w + a1.w) * inn;
    g_e2[v * D4 + lane] = emb;
}

// ---------------------------------------------------------------------------
// layer 3: gather from e2; epilogue writes out = e0 + e1/2 + e2/3 + emb3/4
// ---------------------------------------------------------------------------
__global__ void __launch_bounds__(256)
layer3_kernel(const float4* __restrict__ ue, const float4* __restrict__ ie,
              float4* __restrict__ out) {
    int t    = blockIdx.x * blockDim.x + threadIdx.x;
    int lane = t & 15;
    int v    = t >> 4;
    if (v >= N_NODES) return;
    int beg = __ldg(&g_off[v]);
    int end = __ldg(&g_off[v + 1]);

#define ROW_E2(s) (g_e2 + (size_t)(s) * D4)
    GATHER_LOOP(ROW_E2)
#undef ROW_E2

    float inn = __ldg(&g_in_norm[v]);
    float4 e3;
    e3.x = (a0.x + a1.x) * inn;
    e3.y = (a0.y + a1.y) * inn;
    e3.z = (a0.z + a1.z) * inn;
    e3.w = (a0.w + a1.w) * inn;

    int idx = v * D4 + lane;
    float4 e0 = __ldg(e0_row(ue, ie, v) + lane);
    float4 e1 = g_e1[idx];
    float4 e2 = g_e2[idx];

    const float s1 = 1.f / 2.f, s2 = 1.f / 3.f, s3 = 1.f / 4.f;
    float4 o;
    o.x = e0.x + e1.x * s1 + e2.x * s2 + e3.x * s3;
    o.y = e0.y + e1.y * s1 + e2.y * s2 + e3.y * s3;
    o.z = e0.z + e1.z * s1 + e2.z * s2 + e3.z * s3;
    o.w = e0.w + e1.w * s1 + e2.w * s2 + e3.w * s3;
    out[idx] = o;
}

// ---------------------------------------------------------------------------
// launch
// ---------------------------------------------------------------------------
extern "C" void kernel_launch(void* const* d_in, const int* in_sizes, int n_in,
                              void* d_out, int out_size) {
    const float4* ue  = (const float4*)d_in[0];
    const float4* ie  = (const float4*)d_in[1];
    const int*    src = (const int*)d_in[2];
    const int*    dst = (const int*)d_in[3];
    float4*       out = (float4*)d_out;

    const int T = 256;
    const int gEdge  = (NE + T - 1) / T;
    const int gEdge4 = (NE / 4 + T - 1) / T;
    const int gNode  = (N_NODES + T - 1) / T;
    const int gLayer = (N_NODES * 16 + T - 1) / T;

    zero_kernel<<<gNode, T>>>();
    deg_kernel<<<gEdge4, T>>>((const int4*)src, (const int4*)dst);
    scan1_kernel<<<SCAN_NB, SCAN_B>>>();
    scan2_kernel<<<1, 256>>>();
    scan3_kernel<<<gNode, T>>>();
    fill_kernel<<<gEdge, T>>>(src, dst);

    layer1_kernel<<<gLayer, T>>>(ue, ie);
    layer2_kernel<<<gLayer, T>>>();
    layer3_kernel<<<gLayer, T>>>(ue, ie, out);
}